// round 2
// baseline (speedup 1.0000x reference)
#include <cuda_runtime.h>

#define BSZ   128
#define NIN   784
#define NHID  1024
#define NOUT  10
#define TT    200
#define NPAIR (TT * BSZ)          // 25600
#define ALPHA 0.05f

#define HTILE 64
#define NPG   37
#define PPG   692                  // ceil(25600/37)

// Scratch (static device globals — no runtime allocation)
__device__ float          g_Ih[(size_t)NPAIR * NHID];     // (t*B+b, h)
__device__ unsigned short g_idx[(size_t)NPAIR * NIN];     // active-input lists
__device__ int            g_cnt[NPAIR];

// -------------------------------------------------------------------------
// k1: compact the Bernoulli(0.1) input spikes into per-(t,b) index lists.
// spikes layout: (B, NIN, T). Warp lanes take consecutive t -> coalesced reads.
// -------------------------------------------------------------------------
__global__ void k_compact(const float* __restrict__ sp) {
    int b = blockIdx.x;
    int t = threadIdx.x;
    if (t >= TT) return;
    int pid = t * BSZ + b;
    unsigned short* lst = g_idx + (size_t)pid * NIN;
    const float* base = sp + (size_t)b * NIN * TT + t;
    int cnt = 0;
    #pragma unroll 4
    for (int i = 0; i < NIN; i++) {
        float v = base[(size_t)i * TT];
        if (v > 0.5f) lst[cnt++] = (unsigned short)i;
    }
    g_cnt[pid] = cnt;
}

// -------------------------------------------------------------------------
// k2: sparse accumulate I_h. Block = (h-tile of 64, pair-group).
// w1 tile (784 x 64 fp32 = 200KB) lives in SMEM; each active index adds one
// 64-wide row slice. 16 threads per pair (4 h each, float4), 16 pairs/warp-pair.
// -------------------------------------------------------------------------
__global__ void __launch_bounds__(256, 1) k_sparse_gemm(const float* __restrict__ w1) {
    extern __shared__ float w1s[];            // NIN * HTILE floats
    const int h0 = blockIdx.x * HTILE;

    for (int l = threadIdx.x; l < NIN * HTILE; l += 256) {
        int i = l >> 6, h = l & 63;
        w1s[l] = fmaxf(w1[(size_t)i * NHID + h0 + h], 0.0f);  // relu(w1)
    }
    __syncthreads();

    const int slot = threadIdx.x >> 4;        // 0..15: pair slot
    const int hq   = (threadIdx.x & 15) << 2; // 4-float h offset within tile
    const int p0 = blockIdx.y * PPG;
    const int p1 = (p0 + PPG < NPAIR) ? (p0 + PPG) : NPAIR;

    for (int p = p0 + slot; p < p1; p += 16) {
        const int cnt = g_cnt[p];
        const unsigned short* lst = g_idx + (size_t)p * NIN;
        float4 acc = make_float4(0.f, 0.f, 0.f, 0.f);

        int k = 0;
        for (; k + 8 <= cnt; k += 8) {
            uint4 w = *reinterpret_cast<const uint4*>(lst + k);
            unsigned id[8];
            id[0] = w.x & 0xFFFFu; id[1] = w.x >> 16;
            id[2] = w.y & 0xFFFFu; id[3] = w.y >> 16;
            id[4] = w.z & 0xFFFFu; id[5] = w.z >> 16;
            id[6] = w.w & 0xFFFFu; id[7] = w.w >> 16;
            #pragma unroll
            for (int j = 0; j < 8; j++) {
                const float4 r = *reinterpret_cast<const float4*>(w1s + id[j] * HTILE + hq);
                acc.x += r.x; acc.y += r.y; acc.z += r.z; acc.w += r.w;
            }
        }
        for (; k < cnt; k++) {
            const float4 r = *reinterpret_cast<const float4*>(w1s + (int)lst[k] * HTILE + hq);
            acc.x += r.x; acc.y += r.y; acc.z += r.z; acc.w += r.w;
        }
        *reinterpret_cast<float4*>(g_Ih + (size_t)p * NHID + h0 + hq) = acc;
    }
}

// -------------------------------------------------------------------------
// k3: hidden LIF. One thread per (b,h); 40-step register-staged chunks so
// hidden_spikes (B, NHID, T) writes are 10x float4 contiguous per thread.
// Reads of g_Ih are warp-coalesced (consecutive h).
// -------------------------------------------------------------------------
__global__ void k_lif_hidden(float* __restrict__ hs_out) {
    const int bh = blockIdx.x * 256 + threadIdx.x;
    const int b = bh >> 10;
    const int h = bh & 1023;
    const float* Ibase = g_Ih + (size_t)b * NHID + h;
    float* obase = hs_out + (size_t)bh * TT;

    float v = 0.0f;
    for (int tc = 0; tc < TT; tc += 40) {
        float rr[40];
        #pragma unroll
        for (int j = 0; j < 40; j++) {
            float I = Ibase[(size_t)(tc + j) * (BSZ * NHID)];
            // v = v + ALPHA*(0 - v) + I  (reference association, fp32 exact)
            v = __fadd_rn(__fadd_rn(v, __fmul_rn(ALPHA, -v)), I);
            float s = (v >= 1.0f) ? 1.0f : 0.0f;
            if (v >= 1.0f) v = 0.0f;
            rr[j] = s;
        }
        #pragma unroll
        for (int q = 0; q < 10; q++) {
            float4 o4 = make_float4(rr[4*q], rr[4*q+1], rr[4*q+2], rr[4*q+3]);
            *reinterpret_cast<float4*>(obase + tc + 4*q) = o4;
        }
    }
}

// -------------------------------------------------------------------------
// k4: output layer. I_o[t] = s_h[t-1] . relu(w2).
// Hidden spikes are nearly all 1.0 (E[I_h] ~ 3.9 >> 1), so compute
// I_o = colsum(w2) - sum over {h : s==0}. Then LIF + firing rates.
// -------------------------------------------------------------------------
__global__ void __launch_bounds__(256, 1) k_output(const float* __restrict__ w2,
                                                   const float* __restrict__ hs,
                                                   float* __restrict__ os_out,
                                                   float* __restrict__ fr_out) {
    __shared__ float w2s[NOUT][NHID];   // transposed: conflict-free per-o reads
    __shared__ float Iall[TT][NOUT];
    __shared__ float colsum[NOUT];

    const int b = blockIdx.x;
    const int tid = threadIdx.x;
    const int warp = tid >> 5, lane = tid & 31;

    for (int l = tid; l < NHID * NOUT; l += 256) {
        int h = l / NOUT, o = l % NOUT;
        w2s[o][h] = fmaxf(w2[l], 0.0f);  // relu(w2)
    }
    __syncthreads();

    for (int o = warp; o < NOUT; o += 8) {
        float s = 0.0f;
        for (int h = lane; h < NHID; h += 32) s += w2s[o][h];
        #pragma unroll
        for (int m = 16; m; m >>= 1) s += __shfl_xor_sync(0xFFFFFFFFu, s, m);
        if (lane == 0) colsum[o] = s;
    }
    __syncthreads();

    // Phase A: per-warp contiguous t-range, gate loads on rare s==0
    const int t0 = warp * 25;
    for (int t = t0; t < t0 + 25; t++) {
        float neg[NOUT];
        #pragma unroll
        for (int o = 0; o < NOUT; o++) neg[o] = 0.0f;
        const int tprev = t - 1;
        const bool any = (tprev >= 0);
        if (any) {
            for (int h = lane; h < NHID; h += 32) {
                float s = hs[((size_t)b * NHID + h) * TT + tprev];
                if (s < 0.5f) {
                    #pragma unroll
                    for (int o = 0; o < NOUT; o++) neg[o] += w2s[o][h];
                }
            }
        }
        #pragma unroll
        for (int o = 0; o < NOUT; o++) {
            #pragma unroll
            for (int m = 16; m; m >>= 1)
                neg[o] += __shfl_xor_sync(0xFFFFFFFFu, neg[o], m);
        }
        if (lane == 0) {
            #pragma unroll
            for (int o = 0; o < NOUT; o++)
                Iall[t][o] = any ? (colsum[o] - neg[o]) : 0.0f;
        }
    }
    __syncthreads();

    // Phase B: sequential LIF on outputs + firing rates
    if (tid < NOUT) {
        const int o = tid;
        float v = 0.0f, cnt = 0.0f;
        float* ob = os_out + ((size_t)b * NOUT + o) * TT;
        for (int t = 0; t < TT; t++) {
            float I = Iall[t][o];
            v = __fadd_rn(__fadd_rn(v, __fmul_rn(ALPHA, -v)), I);
            float s = (v >= 1.0f) ? 1.0f : 0.0f;
            if (v >= 1.0f) v = 0.0f;
            ob[t] = s;
            cnt += s;
        }
        fr_out[(size_t)b * NOUT + o] = cnt / (float)TT;
    }
}

// -------------------------------------------------------------------------
extern "C" void kernel_launch(void* const* d_in, const int* in_sizes, int n_in,
                              void* d_out, int out_size) {
    const float* sp = (const float*)d_in[0];   // (128, 784, 200)
    const float* w1 = (const float*)d_in[1];   // (784, 1024)
    const float* w2 = (const float*)d_in[2];   // (1024, 10)

    float* hs = (float*)d_out;                          // (B, NHID, T)
    float* os = hs + (size_t)BSZ * NHID * TT;           // (B, NOUT, T)
    float* fr = os + (size_t)BSZ * NOUT * TT;           // (B, NOUT)

    cudaFuncSetAttribute(k_sparse_gemm,
                         cudaFuncAttributeMaxDynamicSharedMemorySize,
                         NIN * HTILE * (int)sizeof(float));

    k_compact<<<BSZ, 256>>>(sp);
    dim3 g2(NHID / HTILE, NPG);
    k_sparse_gemm<<<g2, 256, NIN * HTILE * sizeof(float)>>>(w1);
    k_lif_hidden<<<(BSZ * NHID) / 256, 256>>>(hs);
    k_output<<<BSZ, 256>>>(w2, hs, os, fr);
}

// round 3
// speedup vs baseline: 1.5126x; 1.5126x over previous
#include <cuda_runtime.h>

#define BSZ   128
#define NIN   784
#define NHID  1024
#define NOUT  10
#define TT    200
#define NPAIR (TT * BSZ)          // 25600
#define ALPHA 0.05f

#define HTILE 64
#define NPG   9
#define PPG   2845                 // ceil(25600/9)
#define K2THREADS 512
#define K2SLOTS   32               // K2THREADS/16

#define HS    4                    // h-splits for output layer

// Scratch (static device globals — no runtime allocation)
__device__ float          g_Ih[(size_t)NPAIR * NHID];     // (t*B+b, h)
__device__ unsigned short g_idx[(size_t)NPAIR * NIN];     // active-input lists
__device__ int            g_cnt[NPAIR];
__device__ float          g_part[(size_t)BSZ * HS * TT * NOUT]; // neg partials

// -------------------------------------------------------------------------
// k1: compact the Bernoulli(0.1) input spikes into per-(t,b) index lists.
// spikes layout: (B, NIN, T). Warp lanes take consecutive t -> coalesced.
// -------------------------------------------------------------------------
__global__ void k_compact(const float* __restrict__ sp) {
    int b = blockIdx.x;
    int t = threadIdx.x;
    if (t >= TT) return;
    int pid = t * BSZ + b;
    unsigned short* lst = g_idx + (size_t)pid * NIN;
    const float* base = sp + (size_t)b * NIN * TT + t;
    int cnt = 0;
    #pragma unroll 4
    for (int i = 0; i < NIN; i++) {
        float v = base[(size_t)i * TT];
        if (v > 0.5f) lst[cnt++] = (unsigned short)i;
    }
    g_cnt[pid] = cnt;
}

// -------------------------------------------------------------------------
// k2: sparse accumulate I_h. Block = (h-tile of 64, pair-group).
// w1 tile (784 x 64 fp32 = 200KB) in SMEM; 512 threads = 32 pair-slots of
// 16 threads (4 h each, float4). 16 warps/SM to saturate the LDS crossbar.
// -------------------------------------------------------------------------
__global__ void __launch_bounds__(K2THREADS, 1) k_sparse_gemm(const float* __restrict__ w1) {
    extern __shared__ float w1s[];            // NIN * HTILE floats
    const int h0 = blockIdx.x * HTILE;

    for (int l = threadIdx.x; l < NIN * HTILE; l += K2THREADS) {
        int i = l >> 6, h = l & 63;
        w1s[l] = fmaxf(w1[(size_t)i * NHID + h0 + h], 0.0f);  // relu(w1)
    }
    __syncthreads();

    const int slot = threadIdx.x >> 4;        // 0..31: pair slot
    const int hq   = (threadIdx.x & 15) << 2; // 4-float h offset within tile
    const int p0 = blockIdx.y * PPG;
    const int p1 = (p0 + PPG < NPAIR) ? (p0 + PPG) : NPAIR;

    for (int p = p0 + slot; p < p1; p += K2SLOTS) {
        const int cnt = g_cnt[p];
        const unsigned short* lst = g_idx + (size_t)p * NIN;
        float4 acc = make_float4(0.f, 0.f, 0.f, 0.f);

        int k = 0;
        for (; k + 8 <= cnt; k += 8) {
            uint4 w = *reinterpret_cast<const uint4*>(lst + k);
            unsigned id[8];
            id[0] = w.x & 0xFFFFu; id[1] = w.x >> 16;
            id[2] = w.y & 0xFFFFu; id[3] = w.y >> 16;
            id[4] = w.z & 0xFFFFu; id[5] = w.z >> 16;
            id[6] = w.w & 0xFFFFu; id[7] = w.w >> 16;
            #pragma unroll
            for (int j = 0; j < 8; j++) {
                const float4 r = *reinterpret_cast<const float4*>(w1s + id[j] * HTILE + hq);
                acc.x += r.x; acc.y += r.y; acc.z += r.z; acc.w += r.w;
            }
        }
        for (; k < cnt; k++) {
            const float4 r = *reinterpret_cast<const float4*>(w1s + (int)lst[k] * HTILE + hq);
            acc.x += r.x; acc.y += r.y; acc.z += r.z; acc.w += r.w;
        }
        *reinterpret_cast<float4*>(g_Ih + (size_t)p * NHID + h0 + hq) = acc;
    }
}

// -------------------------------------------------------------------------
// k3: hidden LIF. One thread per (b,h); 40-step register-staged chunks so
// hidden_spikes (B, NHID, T) writes are float4-contiguous per thread.
// -------------------------------------------------------------------------
__global__ void k_lif_hidden(float* __restrict__ hs_out) {
    const int bh = blockIdx.x * 256 + threadIdx.x;
    const int b = bh >> 10;
    const int h = bh & 1023;
    const float* Ibase = g_Ih + (size_t)b * NHID + h;
    float* obase = hs_out + (size_t)bh * TT;

    float v = 0.0f;
    for (int tc = 0; tc < TT; tc += 40) {
        float rr[40];
        #pragma unroll
        for (int j = 0; j < 40; j++) {
            float I = Ibase[(size_t)(tc + j) * (BSZ * NHID)];
            v = __fadd_rn(__fadd_rn(v, __fmul_rn(ALPHA, -v)), I);
            float s = (v >= 1.0f) ? 1.0f : 0.0f;
            if (v >= 1.0f) v = 0.0f;
            rr[j] = s;
        }
        #pragma unroll
        for (int q = 0; q < 10; q++) {
            float4 o4 = make_float4(rr[4*q], rr[4*q+1], rr[4*q+2], rr[4*q+3]);
            *reinterpret_cast<float4*>(obase + tc + 4*q) = o4;
        }
    }
}

// -------------------------------------------------------------------------
// k4a: parallel neg-sums for the output layer.
// grid = (B, HS). Block 256 threads = 8 warps; warp w owns t = 32w + lane
// (coalesced hs reads over t). Each block scans its 256-h slice; every
// hidden-spike element is read exactly once. Rare s==0 -> add 10 w2 values
// (SMEM broadcast). Writes neg partials to g_part[b][hs][t][o].
// -------------------------------------------------------------------------
__global__ void __launch_bounds__(256, 4) k_out_partials(const float* __restrict__ w2,
                                                         const float* __restrict__ hs) {
    __shared__ float w2s[NOUT][256];
    const int b  = blockIdx.x;
    const int hp = blockIdx.y;
    const int h0 = hp * 256;
    const int tid = threadIdx.x;
    const int warp = tid >> 5, lane = tid & 31;
    const int t = warp * 32 + lane;

    for (int l = tid; l < 256 * NOUT; l += 256) {
        int h = l >> 4;             // 0..255 (16 per... careful)
        // l = h'*10 + o is awkward; use direct mapping:
        ;
    }
    // straightforward staging: each thread loads 10 values for its h'
    {
        int hh = tid;               // 0..255
        #pragma unroll
        for (int o = 0; o < NOUT; o++)
            w2s[o][hh] = fmaxf(w2[(size_t)(h0 + hh) * NOUT + o], 0.0f);
    }
    __syncthreads();

    float neg[NOUT];
    #pragma unroll
    for (int o = 0; o < NOUT; o++) neg[o] = 0.0f;

    if (t < TT) {
        const float* sbase = hs + ((size_t)b * NHID + h0) * TT + t;
        for (int hh = 0; hh < 256; hh++) {
            float s = sbase[(size_t)hh * TT];
            if (s < 0.5f) {
                #pragma unroll
                for (int o = 0; o < NOUT; o++) neg[o] += w2s[o][hh];
            }
        }
        float* pb = g_part + (((size_t)b * HS + hp) * TT + t) * NOUT;
        #pragma unroll
        for (int o = 0; o < NOUT; o++) pb[o] = neg[o];
    }
}

// -------------------------------------------------------------------------
// k4b: sequential output LIF + firing rates. 1280 threads = (b, o).
// I_o(t) = (t>0) ? colsum_o - sum_p neg[b][p][t-1][o] : 0.
// -------------------------------------------------------------------------
__global__ void k_out_lif(const float* __restrict__ w2,
                          float* __restrict__ os_out,
                          float* __restrict__ fr_out) {
    const int gid = blockIdx.x * blockDim.x + threadIdx.x;
    if (gid >= BSZ * NOUT) return;
    const int b = gid / NOUT;
    const int o = gid - b * NOUT;

    float colsum = 0.0f;
    for (int h = 0; h < NHID; h++)
        colsum += fmaxf(w2[(size_t)h * NOUT + o], 0.0f);

    const float* pb = g_part + ((size_t)b * HS) * TT * NOUT + o;
    float v = 0.0f, cnt = 0.0f;
    float* ob = os_out + ((size_t)b * NOUT + o) * TT;
    for (int t = 0; t < TT; t++) {
        float I = 0.0f;
        if (t > 0) {
            float neg = 0.0f;
            #pragma unroll
            for (int p = 0; p < HS; p++)
                neg += pb[((size_t)p * TT + (t - 1)) * NOUT];
            I = colsum - neg;
        }
        v = __fadd_rn(__fadd_rn(v, __fmul_rn(ALPHA, -v)), I);
        float s = (v >= 1.0f) ? 1.0f : 0.0f;
        if (v >= 1.0f) v = 0.0f;
        ob[t] = s;
        cnt += s;
    }
    fr_out[gid] = cnt / (float)TT;
}

// -------------------------------------------------------------------------
extern "C" void kernel_launch(void* const* d_in, const int* in_sizes, int n_in,
                              void* d_out, int out_size) {
    const float* sp = (const float*)d_in[0];   // (128, 784, 200)
    const float* w1 = (const float*)d_in[1];   // (784, 1024)
    const float* w2 = (const float*)d_in[2];   // (1024, 10)

    float* hs = (float*)d_out;                          // (B, NHID, T)
    float* os = hs + (size_t)BSZ * NHID * TT;           // (B, NOUT, T)
    float* fr = os + (size_t)BSZ * NOUT * TT;           // (B, NOUT)

    cudaFuncSetAttribute(k_sparse_gemm,
                         cudaFuncAttributeMaxDynamicSharedMemorySize,
                         NIN * HTILE * (int)sizeof(float));

    k_compact<<<BSZ, 256>>>(sp);
    dim3 g2(NHID / HTILE, NPG);
    k_sparse_gemm<<<g2, K2THREADS, NIN * HTILE * sizeof(float)>>>(w1);
    k_lif_hidden<<<(BSZ * NHID) / 256, 256>>>(hs);
    dim3 g4(BSZ, HS);
    k_out_partials<<<g4, 256>>>(w2, hs);
    k_out_lif<<<5, 256>>>(w2, os, fr);
}

// round 6
// speedup vs baseline: 2.1510x; 1.4220x over previous
#include <cuda_runtime.h>
#include <cuda_fp16.h>
#include <cstdint>

#define BSZ   128
#define NIN   784
#define NHID  1024
#define NOUT  10
#define TT    200
#define NPAIR (TT * BSZ)          // 25600
#define ALPHA 0.05f
#define KPAD  832                  // 13 * 64 (K padded with zeros)
#define NCH   13                   // K chunks of 64
#define HS    8                    // h-splits for output layer

#define SAPITCH 68                 // padded half-stride for SMEM tiles

// -------------------- scratch (static device globals) ---------------------
__device__ unsigned short g_A[(size_t)NPAIR * KPAD];   // fp16 spikes  (pair, k)
__device__ unsigned short g_B[(size_t)NHID * KPAD];    // fp16 relu(w1)^T (n, k)
__device__ float          g_Ih[(size_t)NPAIR * NHID];  // (pair, h)
__device__ float          g_part[(size_t)BSZ * HS * TT * NOUT];

// --------------------------------------------------------------------------
// kA: stage spikes as fp16 A[(t*B+b), i] with K padded to 832. Coalesced via
// SMEM (i,t) tile transpose per b.
// --------------------------------------------------------------------------
__global__ void __launch_bounds__(256) kA_stage(const float* __restrict__ sp) {
    extern __shared__ float tile[];   // [32][201]
    const int b = blockIdx.x;
    const int i0 = blockIdx.y * 32;
    for (int l = threadIdx.x; l < 32 * 200; l += 256) {
        int ii = l / 200, t = l - ii * 200;
        int i = i0 + ii;
        float v = (i < NIN) ? sp[((size_t)b * NIN + i) * TT + t] : 0.0f;
        tile[ii * 201 + t] = v;
    }
    __syncthreads();
    __half* A = (__half*)g_A;
    for (int l = threadIdx.x; l < 32 * 200; l += 256) {
        int t = l >> 5, ii = l & 31;
        A[((size_t)t * BSZ + b) * KPAD + i0 + ii] = __float2half(tile[ii * 201 + t]);
    }
}

// --------------------------------------------------------------------------
// kB: stage relu(w1)^T as fp16 B[n, i], K padded to 832.
// --------------------------------------------------------------------------
__global__ void __launch_bounds__(256) kB_stage(const float* __restrict__ w1) {
    __shared__ float tile[32][33];
    const int n0 = blockIdx.x * 32;
    const int i0 = blockIdx.y * 32;
    const int r = threadIdx.x >> 5, c = threadIdx.x & 31;
    for (int rr = r; rr < 32; rr += 8) {
        int i = i0 + rr;
        tile[rr][c] = (i < NIN) ? fmaxf(w1[(size_t)i * NHID + n0 + c], 0.0f) : 0.0f;
    }
    __syncthreads();
    __half* B = (__half*)g_B;
    for (int cc = r; cc < 32; cc += 8)
        B[((size_t)(n0 + cc)) * KPAD + i0 + c] = __float2half(tile[c][cc]);
}

// --------------------------------------------------------------------------
// k_gemm: I_h = A(25600x832 fp16) @ B^T(1024x832 fp16), fp32 accum, via
// mma.sync.m16n8k16 (baseline-PTX HMMA; tcgen05 unavailable on sm_103 target).
// CTA 128x128, K chunks of 64, software-pipelined global->smem staging.
// Warps: 4(M) x 2(N); warp tile 32(M) x 64(N) -> 2x8 mma tiles, 64 accums.
// --------------------------------------------------------------------------
__device__ __forceinline__ void mma16816(float* c, uint32_t a0, uint32_t a1,
                                         uint32_t a2, uint32_t a3,
                                         uint32_t b0, uint32_t b1) {
    asm volatile(
        "mma.sync.aligned.m16n8k16.row.col.f32.f16.f16.f32 "
        "{%0,%1,%2,%3}, {%4,%5,%6,%7}, {%8,%9}, {%0,%1,%2,%3};"
        : "+f"(c[0]), "+f"(c[1]), "+f"(c[2]), "+f"(c[3])
        : "r"(a0), "r"(a1), "r"(a2), "r"(a3), "r"(b0), "r"(b1));
}

__global__ void __launch_bounds__(256, 2) k_gemm() {
    __shared__ __half sA[128 * SAPITCH];
    __shared__ __half sB[128 * SAPITCH];

    const int tid  = threadIdx.x;
    const int warp = tid >> 5, lane = tid & 31;
    const int wm = warp & 3;            // 0..3 -> m offset 32*wm
    const int wn = warp >> 2;           // 0..1 -> n offset 64*wn
    const int p0 = blockIdx.x * 128;
    const int n0 = blockIdx.y * 128;
    const __half* A  = (const __half*)g_A;
    const __half* Bm = (const __half*)g_B;

    // Per-thread staging slice: 16 uint2 (8 for A, 8 for B).
    // A: 128 rows x 16 uint2/row = 2048; thread covers idx = j*256+tid.
    uint2 st[16];

    const int arow[8] = { (0*256+tid) >> 4, (1*256+tid) >> 4, (2*256+tid) >> 4, (3*256+tid) >> 4,
                          (4*256+tid) >> 4, (5*256+tid) >> 4, (6*256+tid) >> 4, (7*256+tid) >> 4 };
    const int acol = (tid & 15) * 4;    // half offset within 64-half row

    float acc[2][8][4];
    #pragma unroll
    for (int mt = 0; mt < 2; mt++)
        #pragma unroll
        for (int nt = 0; nt < 8; nt++)
            #pragma unroll
            for (int q = 0; q < 4; q++) acc[mt][nt][q] = 0.0f;

    // prologue: load chunk 0
    #pragma unroll
    for (int j = 0; j < 8; j++) {
        st[j]     = *reinterpret_cast<const uint2*>(A  + (size_t)(p0 + arow[j]) * KPAD + acol);
        st[j + 8] = *reinterpret_cast<const uint2*>(Bm + (size_t)(n0 + arow[j]) * KPAD + acol);
    }

    #pragma unroll 1
    for (int c = 0; c < NCH; c++) {
        __syncthreads();   // previous compute done
        #pragma unroll
        for (int j = 0; j < 8; j++) {
            *reinterpret_cast<uint2*>(sA + arow[j] * SAPITCH + acol) = st[j];
            *reinterpret_cast<uint2*>(sB + arow[j] * SAPITCH + acol) = st[j + 8];
        }
        __syncthreads();

        if (c + 1 < NCH) {
            const size_t kof = (size_t)(c + 1) * 64;
            #pragma unroll
            for (int j = 0; j < 8; j++) {
                st[j]     = *reinterpret_cast<const uint2*>(A  + (size_t)(p0 + arow[j]) * KPAD + kof + acol);
                st[j + 8] = *reinterpret_cast<const uint2*>(Bm + (size_t)(n0 + arow[j]) * KPAD + kof + acol);
            }
        }

        // compute: 4 k-steps of 16
        #pragma unroll
        for (int ks = 0; ks < 4; ks++) {
            const int kc = ks * 16 + (lane & 3) * 2;
            uint32_t af[2][4];
            #pragma unroll
            for (int mt = 0; mt < 2; mt++) {
                const int r = wm * 32 + mt * 16 + (lane >> 2);
                af[mt][0] = *reinterpret_cast<const uint32_t*>(sA + r * SAPITCH + kc);
                af[mt][1] = *reinterpret_cast<const uint32_t*>(sA + (r + 8) * SAPITCH + kc);
                af[mt][2] = *reinterpret_cast<const uint32_t*>(sA + r * SAPITCH + kc + 8);
                af[mt][3] = *reinterpret_cast<const uint32_t*>(sA + (r + 8) * SAPITCH + kc + 8);
            }
            #pragma unroll
            for (int nt = 0; nt < 8; nt++) {
                const int n = wn * 64 + nt * 8 + (lane >> 2);
                uint32_t b0 = *reinterpret_cast<const uint32_t*>(sB + n * SAPITCH + kc);
                uint32_t b1 = *reinterpret_cast<const uint32_t*>(sB + n * SAPITCH + kc + 8);
                mma16816(acc[0][nt], af[0][0], af[0][1], af[0][2], af[0][3], b0, b1);
                mma16816(acc[1][nt], af[1][0], af[1][1], af[1][2], af[1][3], b0, b1);
            }
        }
    }

    // epilogue: write fp32 results
    #pragma unroll
    for (int mt = 0; mt < 2; mt++) {
        const int m = p0 + wm * 32 + mt * 16 + (lane >> 2);
        #pragma unroll
        for (int nt = 0; nt < 8; nt++) {
            const int n = n0 + wn * 64 + nt * 8 + (lane & 3) * 2;
            float2 lo = make_float2(acc[mt][nt][0], acc[mt][nt][1]);
            float2 hi = make_float2(acc[mt][nt][2], acc[mt][nt][3]);
            *reinterpret_cast<float2*>(g_Ih + (size_t)m * NHID + n) = lo;
            *reinterpret_cast<float2*>(g_Ih + (size_t)(m + 8) * NHID + n) = hi;
        }
    }
}

// --------------------------------------------------------------------------
// k3: hidden LIF. Thread per (b,h), 40-step register chunks.
// --------------------------------------------------------------------------
__global__ void k_lif_hidden(float* __restrict__ hs_out) {
    const int bh = blockIdx.x * 256 + threadIdx.x;
    const int b = bh >> 10;
    const int h = bh & 1023;
    const float* Ibase = g_Ih + (size_t)b * NHID + h;
    float* obase = hs_out + (size_t)bh * TT;

    float v = 0.0f;
    for (int tc = 0; tc < TT; tc += 40) {
        float rr[40];
        #pragma unroll
        for (int j = 0; j < 40; j++) {
            float I = Ibase[(size_t)(tc + j) * (BSZ * NHID)];
            v = __fadd_rn(__fadd_rn(v, __fmul_rn(ALPHA, -v)), I);
            float s = (v >= 1.0f) ? 1.0f : 0.0f;
            if (v >= 1.0f) v = 0.0f;
            rr[j] = s;
        }
        #pragma unroll
        for (int q = 0; q < 10; q++) {
            float4 o4 = make_float4(rr[4*q], rr[4*q+1], rr[4*q+2], rr[4*q+3]);
            *reinterpret_cast<float4*>(obase + tc + 4*q) = o4;
        }
    }
}

// --------------------------------------------------------------------------
// k4a: parallel neg-sums for output layer. grid (B, HS=8); 128-h slices.
// --------------------------------------------------------------------------
__global__ void __launch_bounds__(256, 8) k_out_partials(const float* __restrict__ w2,
                                                         const float* __restrict__ hs) {
    __shared__ float w2s[NOUT][128];
    const int b  = blockIdx.x;
    const int hp = blockIdx.y;
    const int h0 = hp * 128;
    const int tid = threadIdx.x;
    if (tid < 128) {
        #pragma unroll
        for (int o = 0; o < NOUT; o++)
            w2s[o][tid] = fmaxf(w2[(size_t)(h0 + tid) * NOUT + o], 0.0f);
    }
    __syncthreads();

    const int t = tid;
    if (t >= TT) return;

    float neg[NOUT];
    #pragma unroll
    for (int o = 0; o < NOUT; o++) neg[o] = 0.0f;

    const float* sbase = hs + ((size_t)b * NHID + h0) * TT + t;
    for (int hh = 0; hh < 128; hh++) {
        float s = sbase[(size_t)hh * TT];
        if (s < 0.5f) {
            #pragma unroll
            for (int o = 0; o < NOUT; o++) neg[o] += w2s[o][hh];
        }
    }
    float* pb = g_part + (((size_t)b * HS + hp) * TT + t) * NOUT;
    #pragma unroll
    for (int o = 0; o < NOUT; o++) pb[o] = neg[o];
}

// --------------------------------------------------------------------------
// k4b: sequential output LIF + firing rates. thread per (b,o).
// --------------------------------------------------------------------------
__global__ void k_out_lif(const float* __restrict__ w2,
                          float* __restrict__ os_out,
                          float* __restrict__ fr_out) {
    const int gid = blockIdx.x * blockDim.x + threadIdx.x;
    if (gid >= BSZ * NOUT) return;
    const int b = gid / NOUT;
    const int o = gid - b * NOUT;

    float colsum = 0.0f;
    for (int h = 0; h < NHID; h++)
        colsum += fmaxf(w2[(size_t)h * NOUT + o], 0.0f);

    const float* pb = g_part + ((size_t)b * HS) * TT * NOUT + o;
    float v = 0.0f, cnt = 0.0f;
    float* ob = os_out + ((size_t)b * NOUT + o) * TT;
    for (int t = 0; t < TT; t++) {
        float I = 0.0f;
        if (t > 0) {
            float neg = 0.0f;
            #pragma unroll
            for (int p = 0; p < HS; p++)
                neg += pb[((size_t)p * TT + (t - 1)) * NOUT];
            I = colsum - neg;
        }
        v = __fadd_rn(__fadd_rn(v, __fmul_rn(ALPHA, -v)), I);
        float s = (v >= 1.0f) ? 1.0f : 0.0f;
        if (v >= 1.0f) v = 0.0f;
        ob[t] = s;
        cnt += s;
    }
    fr_out[gid] = cnt / (float)TT;
}

// --------------------------------------------------------------------------
extern "C" void kernel_launch(void* const* d_in, const int* in_sizes, int n_in,
                              void* d_out, int out_size) {
    const float* sp = (const float*)d_in[0];   // (128, 784, 200)
    const float* w1 = (const float*)d_in[1];   // (784, 1024)
    const float* w2 = (const float*)d_in[2];   // (1024, 10)

    float* hs = (float*)d_out;                          // (B, NHID, T)
    float* os = hs + (size_t)BSZ * NHID * TT;           // (B, NOUT, T)
    float* fr = os + (size_t)BSZ * NOUT * TT;           // (B, NOUT)

    kA_stage<<<dim3(BSZ, 26), 256, 32 * 201 * sizeof(float)>>>(sp);
    kB_stage<<<dim3(32, 26), 256>>>(w1);
    k_gemm<<<dim3(NPAIR / 128, NHID / 128), 256>>>();
    k_lif_hidden<<<(BSZ * NHID) / 256, 256>>>(hs);
    k_out_partials<<<dim3(BSZ, HS), 256>>>(w2, hs);
    k_out_lif<<<5, 256>>>(w2, os, fr);
}

// round 7
// speedup vs baseline: 2.3945x; 1.1132x over previous
#include <cuda_runtime.h>
#include <cuda_fp16.h>
#include <cstdint>

#define BSZ   128
#define NIN   784
#define NHID  1024
#define NOUT  10
#define TT    200
#define NPAIR (TT * BSZ)          // 25600
#define ALPHA 0.05f
#define KPAD  832                  // 13 * 64 (K padded with zeros)
#define NCH   13                   // K chunks of 64

#define SAPITCH 68                 // padded half-stride for SMEM tiles

// -------------------- scratch (static device globals) ---------------------
__device__ unsigned short g_A[(size_t)NPAIR * KPAD];   // fp16 spikes  (pair, k)
__device__ unsigned short g_B[(size_t)NHID * KPAD];    // fp16 relu(w1)^T (n, k)
__device__ float          g_Ih[(size_t)NPAIR * NHID];  // (pair, h)
__device__ float          g_part[(size_t)BSZ * TT * NOUT]; // neg sums (b,t,o)

// --------------------------------------------------------------------------
// kA: stage spikes as fp16 A[(t*B+b), i] with K padded to 832.
// --------------------------------------------------------------------------
__global__ void __launch_bounds__(256) kA_stage(const float* __restrict__ sp) {
    extern __shared__ float tile[];   // [32][201]
    const int b = blockIdx.x;
    const int i0 = blockIdx.y * 32;
    for (int l = threadIdx.x; l < 32 * 200; l += 256) {
        int ii = l / 200, t = l - ii * 200;
        int i = i0 + ii;
        float v = (i < NIN) ? sp[((size_t)b * NIN + i) * TT + t] : 0.0f;
        tile[ii * 201 + t] = v;
    }
    __syncthreads();
    __half* A = (__half*)g_A;
    for (int l = threadIdx.x; l < 32 * 200; l += 256) {
        int t = l >> 5, ii = l & 31;
        A[((size_t)t * BSZ + b) * KPAD + i0 + ii] = __float2half(tile[ii * 201 + t]);
    }
}

// --------------------------------------------------------------------------
// kB: stage relu(w1)^T as fp16 B[n, i], K padded to 832.
// --------------------------------------------------------------------------
__global__ void __launch_bounds__(256) kB_stage(const float* __restrict__ w1) {
    __shared__ float tile[32][33];
    const int n0 = blockIdx.x * 32;
    const int i0 = blockIdx.y * 32;
    const int r = threadIdx.x >> 5, c = threadIdx.x & 31;
    for (int rr = r; rr < 32; rr += 8) {
        int i = i0 + rr;
        tile[rr][c] = (i < NIN) ? fmaxf(w1[(size_t)i * NHID + n0 + c], 0.0f) : 0.0f;
    }
    __syncthreads();
    __half* B = (__half*)g_B;
    for (int cc = r; cc < 32; cc += 8)
        B[((size_t)(n0 + cc)) * KPAD + i0 + c] = __float2half(tile[c][cc]);
}

// --------------------------------------------------------------------------
// k_zero: clear g_part (1.02 MB) each run (graph-replay safe).
// --------------------------------------------------------------------------
__global__ void k_zero() {
    const int idx = (blockIdx.x * 256 + threadIdx.x) * 4;
    if (idx < BSZ * TT * NOUT)
        *reinterpret_cast<float4*>(g_part + idx) = make_float4(0.f, 0.f, 0.f, 0.f);
}

// --------------------------------------------------------------------------
// k_gemm: I_h = A @ B^T via mma.sync.m16n8k16, fp32 accum.
// Grid: x = N-tiles (8, fastest -> consecutive CTAs share the A tile in L2),
//       y = pair-tiles (200). CTA 128x128, double-buffered K chunks of 64.
// --------------------------------------------------------------------------
__device__ __forceinline__ void mma16816(float* c, uint32_t a0, uint32_t a1,
                                         uint32_t a2, uint32_t a3,
                                         uint32_t b0, uint32_t b1) {
    asm volatile(
        "mma.sync.aligned.m16n8k16.row.col.f32.f16.f16.f32 "
        "{%0,%1,%2,%3}, {%4,%5,%6,%7}, {%8,%9}, {%0,%1,%2,%3};"
        : "+f"(c[0]), "+f"(c[1]), "+f"(c[2]), "+f"(c[3])
        : "r"(a0), "r"(a1), "r"(a2), "r"(a3), "r"(b0), "r"(b1));
}

__global__ void __launch_bounds__(256, 2) k_gemm() {
    __shared__ __half sA[128 * SAPITCH];
    __shared__ __half sB[128 * SAPITCH];

    const int tid  = threadIdx.x;
    const int warp = tid >> 5, lane = tid & 31;
    const int wm = warp & 3;
    const int wn = warp >> 2;
    const int n0 = blockIdx.x * 128;
    const int p0 = blockIdx.y * 128;
    const __half* A  = (const __half*)g_A;
    const __half* Bm = (const __half*)g_B;

    uint2 st[16];
    const int arow[8] = { (0*256+tid) >> 4, (1*256+tid) >> 4, (2*256+tid) >> 4, (3*256+tid) >> 4,
                          (4*256+tid) >> 4, (5*256+tid) >> 4, (6*256+tid) >> 4, (7*256+tid) >> 4 };
    const int acol = (tid & 15) * 4;

    float acc[2][8][4];
    #pragma unroll
    for (int mt = 0; mt < 2; mt++)
        #pragma unroll
        for (int nt = 0; nt < 8; nt++)
            #pragma unroll
            for (int q = 0; q < 4; q++) acc[mt][nt][q] = 0.0f;

    #pragma unroll
    for (int j = 0; j < 8; j++) {
        st[j]     = *reinterpret_cast<const uint2*>(A  + (size_t)(p0 + arow[j]) * KPAD + acol);
        st[j + 8] = *reinterpret_cast<const uint2*>(Bm + (size_t)(n0 + arow[j]) * KPAD + acol);
    }

    #pragma unroll 1
    for (int c = 0; c < NCH; c++) {
        __syncthreads();
        #pragma unroll
        for (int j = 0; j < 8; j++) {
            *reinterpret_cast<uint2*>(sA + arow[j] * SAPITCH + acol) = st[j];
            *reinterpret_cast<uint2*>(sB + arow[j] * SAPITCH + acol) = st[j + 8];
        }
        __syncthreads();

        if (c + 1 < NCH) {
            const size_t kof = (size_t)(c + 1) * 64;
            #pragma unroll
            for (int j = 0; j < 8; j++) {
                st[j]     = *reinterpret_cast<const uint2*>(A  + (size_t)(p0 + arow[j]) * KPAD + kof + acol);
                st[j + 8] = *reinterpret_cast<const uint2*>(Bm + (size_t)(n0 + arow[j]) * KPAD + kof + acol);
            }
        }

        #pragma unroll
        for (int ks = 0; ks < 4; ks++) {
            const int kc = ks * 16 + (lane & 3) * 2;
            uint32_t af[2][4];
            #pragma unroll
            for (int mt = 0; mt < 2; mt++) {
                const int r = wm * 32 + mt * 16 + (lane >> 2);
                af[mt][0] = *reinterpret_cast<const uint32_t*>(sA + r * SAPITCH + kc);
                af[mt][1] = *reinterpret_cast<const uint32_t*>(sA + (r + 8) * SAPITCH + kc);
                af[mt][2] = *reinterpret_cast<const uint32_t*>(sA + r * SAPITCH + kc + 8);
                af[mt][3] = *reinterpret_cast<const uint32_t*>(sA + (r + 8) * SAPITCH + kc + 8);
            }
            #pragma unroll
            for (int nt = 0; nt < 8; nt++) {
                const int n = wn * 64 + nt * 8 + (lane >> 2);
                uint32_t b0 = *reinterpret_cast<const uint32_t*>(sB + n * SAPITCH + kc);
                uint32_t b1 = *reinterpret_cast<const uint32_t*>(sB + n * SAPITCH + kc + 8);
                mma16816(acc[0][nt], af[0][0], af[0][1], af[0][2], af[0][3], b0, b1);
                mma16816(acc[1][nt], af[1][0], af[1][1], af[1][2], af[1][3], b0, b1);
            }
        }
    }

    #pragma unroll
    for (int mt = 0; mt < 2; mt++) {
        const int m = p0 + wm * 32 + mt * 16 + (lane >> 2);
        #pragma unroll
        for (int nt = 0; nt < 8; nt++) {
            const int n = n0 + wn * 64 + nt * 8 + (lane & 3) * 2;
            float2 lo = make_float2(acc[mt][nt][0], acc[mt][nt][1]);
            float2 hi = make_float2(acc[mt][nt][2], acc[mt][nt][3]);
            *reinterpret_cast<float2*>(g_Ih + (size_t)m * NHID + n) = lo;
            *reinterpret_cast<float2*>(g_Ih + (size_t)(m + 8) * NHID + n) = hi;
        }
    }
}

// --------------------------------------------------------------------------
// k3: hidden LIF + fused output-layer neg contributions.
// Thread per (b,h); 40-step chunks staged in SMEM for coalesced (.,T) writes.
// s==0 is astronomically rare (v resets to 0, next I ~ N(3.9,0.55)), so the
// atomicAdd path is effectively never taken.
// --------------------------------------------------------------------------
__global__ void __launch_bounds__(256) k_lif_hidden(const float* __restrict__ w2,
                                                    float* __restrict__ hs_out) {
    __shared__ float ss[256 * 41];
    const int tid = threadIdx.x;
    const int warp = tid >> 5, lane = tid & 31;
    const int bh = blockIdx.x * 256 + tid;
    const int b = bh >> 10;
    const int h = bh & 1023;
    const float* Ibase = g_Ih + (size_t)b * NHID + h;
    const int row0 = blockIdx.x * 256;

    float v = 0.0f;
    for (int tc = 0; tc < TT; tc += 40) {
        #pragma unroll
        for (int j = 0; j < 40; j++) {
            float I = Ibase[(size_t)(tc + j) * (BSZ * NHID)];
            v = __fadd_rn(__fadd_rn(v, __fmul_rn(ALPHA, -v)), I);
            float s;
            if (v >= 1.0f) { s = 1.0f; v = 0.0f; }
            else {
                s = 0.0f;
                // rare path: contribute to output-layer neg sums
                float* pb = g_part + ((size_t)b * TT + (tc + j)) * NOUT;
                #pragma unroll
                for (int o = 0; o < NOUT; o++)
                    atomicAdd(pb + o, fmaxf(w2[(size_t)h * NOUT + o], 0.0f));
            }
            ss[tid * 41 + j] = s;
        }
        __syncthreads();
        // warp-transposed coalesced writes: each warp stores its 32 rows
        #pragma unroll 1
        for (int r = 0; r < 32; r++) {
            const int row = warp * 32 + r;
            float* ob = hs_out + (size_t)(row0 + row) * TT + tc;
            #pragma unroll
            for (int j = lane; j < 40; j += 32)
                ob[j] = ss[row * 41 + j];
        }
        __syncthreads();
    }
}

// --------------------------------------------------------------------------
// k4b: sequential output LIF + firing rates. thread per (b,o).
// I_o(t) = (t>0) ? colsum_o - g_part[b][t-1][o] : 0.
// --------------------------------------------------------------------------
__global__ void k_out_lif(const float* __restrict__ w2,
                          float* __restrict__ os_out,
                          float* __restrict__ fr_out) {
    const int gid = blockIdx.x * blockDim.x + threadIdx.x;
    if (gid >= BSZ * NOUT) return;
    const int b = gid / NOUT;
    const int o = gid - b * NOUT;

    float colsum = 0.0f;
    for (int h = 0; h < NHID; h++)
        colsum += fmaxf(w2[(size_t)h * NOUT + o], 0.0f);

    const float* pb = g_part + (size_t)b * TT * NOUT + o;
    float v = 0.0f, cnt = 0.0f;
    float* ob = os_out + ((size_t)b * NOUT + o) * TT;
    for (int t = 0; t < TT; t++) {
        float I = (t > 0) ? (colsum - pb[(size_t)(t - 1) * NOUT]) : 0.0f;
        v = __fadd_rn(__fadd_rn(v, __fmul_rn(ALPHA, -v)), I);
        float s = (v >= 1.0f) ? 1.0f : 0.0f;
        if (v >= 1.0f) v = 0.0f;
        ob[t] = s;
        cnt += s;
    }
    fr_out[gid] = cnt / (float)TT;
}

// --------------------------------------------------------------------------
extern "C" void kernel_launch(void* const* d_in, const int* in_sizes, int n_in,
                              void* d_out, int out_size) {
    const float* sp = (const float*)d_in[0];   // (128, 784, 200)
    const float* w1 = (const float*)d_in[1];   // (784, 1024)
    const float* w2 = (const float*)d_in[2];   // (1024, 10)

    float* hs = (float*)d_out;                          // (B, NHID, T)
    float* os = hs + (size_t)BSZ * NHID * TT;           // (B, NOUT, T)
    float* fr = os + (size_t)BSZ * NOUT * TT;           // (B, NOUT)

    kA_stage<<<dim3(BSZ, 26), 256, 32 * 201 * sizeof(float)>>>(sp);
    kB_stage<<<dim3(32, 26), 256>>>(w1);
    k_zero<<<(BSZ * TT * NOUT / 4 + 255) / 256, 256>>>();
    k_gemm<<<dim3(NHID / 128, NPAIR / 128), 256>>>();
    k_lif_hidden<<<(BSZ * NHID) / 256, 256>>>(w2, hs);
    k_out_lif<<<5, 256>>>(w2, os, fr);
}

// round 8
// speedup vs baseline: 2.7525x; 1.1495x over previous
#include <cuda_runtime.h>
#include <cuda_fp16.h>
#include <cstdint>

#define BSZ   128
#define NIN   784
#define NHID  1024
#define NOUT  10
#define TT    200
#define NPAIR (TT * BSZ)          // 25600
#define ALPHA 0.05f
#define KPAD  832                  // 13 * 64 (K padded with zeros)
#define NCH   13                   // K chunks of 64

// -------------------- scratch (static device globals) ---------------------
__device__ unsigned short g_A[(size_t)NPAIR * KPAD];   // fp16 spikes  (pair, k)
__device__ unsigned short g_B[(size_t)NHID * KPAD];    // fp16 relu(w1)^T (n, k)
__device__ float          g_Ih[(size_t)NPAIR * NHID];  // (pair, h)
__device__ float          g_part[(size_t)BSZ * TT * NOUT]; // neg sums (b,t,o)

// --------------------------------------------------------------------------
// kA: stage spikes as fp16 A[(t*B+b), i] with K padded to 832.
// --------------------------------------------------------------------------
__global__ void __launch_bounds__(256) kA_stage(const float* __restrict__ sp) {
    extern __shared__ float tile[];   // [32][201]
    const int b = blockIdx.x;
    const int i0 = blockIdx.y * 32;
    for (int l = threadIdx.x; l < 32 * 200; l += 256) {
        int ii = l / 200, t = l - ii * 200;
        int i = i0 + ii;
        float v = (i < NIN) ? sp[((size_t)b * NIN + i) * TT + t] : 0.0f;
        tile[ii * 201 + t] = v;
    }
    __syncthreads();
    __half* A = (__half*)g_A;
    for (int l = threadIdx.x; l < 32 * 200; l += 256) {
        int t = l >> 5, ii = l & 31;
        A[((size_t)t * BSZ + b) * KPAD + i0 + ii] = __float2half(tile[ii * 201 + t]);
    }
}

// --------------------------------------------------------------------------
// kB: stage relu(w1)^T as fp16 B[n, i], K padded to 832.
// --------------------------------------------------------------------------
__global__ void __launch_bounds__(256) kB_stage(const float* __restrict__ w1) {
    __shared__ float tile[32][33];
    const int n0 = blockIdx.x * 32;
    const int i0 = blockIdx.y * 32;
    const int r = threadIdx.x >> 5, c = threadIdx.x & 31;
    for (int rr = r; rr < 32; rr += 8) {
        int i = i0 + rr;
        tile[rr][c] = (i < NIN) ? fmaxf(w1[(size_t)i * NHID + n0 + c], 0.0f) : 0.0f;
    }
    __syncthreads();
    __half* B = (__half*)g_B;
    for (int cc = r; cc < 32; cc += 8)
        B[((size_t)(n0 + cc)) * KPAD + i0 + c] = __float2half(tile[c][cc]);
}

// --------------------------------------------------------------------------
// k_zero: clear g_part (1.02 MB) each run (graph-replay safe).
// --------------------------------------------------------------------------
__global__ void k_zero() {
    const int idx = (blockIdx.x * 256 + threadIdx.x) * 4;
    if (idx < BSZ * TT * NOUT)
        *reinterpret_cast<float4*>(g_part + idx) = make_float4(0.f, 0.f, 0.f, 0.f);
}

// --------------------------------------------------------------------------
// k_gemm: I_h = A @ B^T via mma.sync.m16n8k16 + ldmatrix from XOR-swizzled
// SMEM (128B rows, chunk c at c^(row&7)): 6 LDSM.x4 per warp-ks vs 24 LDS.32.
// Grid: x = N-tiles (8, fastest; A tile shared via L2), y = pair-tiles (200).
// --------------------------------------------------------------------------
__device__ __forceinline__ uint32_t smem_u32(const void* p) {
    uint32_t a;
    asm("{ .reg .u64 t; cvta.to.shared.u64 t, %1; cvt.u32.u64 %0, t; }"
        : "=r"(a) : "l"(p));
    return a;
}
__device__ __forceinline__ void mma16816(float* c, uint32_t a0, uint32_t a1,
                                         uint32_t a2, uint32_t a3,
                                         uint32_t b0, uint32_t b1) {
    asm volatile(
        "mma.sync.aligned.m16n8k16.row.col.f32.f16.f16.f32 "
        "{%0,%1,%2,%3}, {%4,%5,%6,%7}, {%8,%9}, {%0,%1,%2,%3};"
        : "+f"(c[0]), "+f"(c[1]), "+f"(c[2]), "+f"(c[3])
        : "r"(a0), "r"(a1), "r"(a2), "r"(a3), "r"(b0), "r"(b1));
}
__device__ __forceinline__ void ldsm4(uint32_t& r0, uint32_t& r1,
                                      uint32_t& r2, uint32_t& r3, uint32_t addr) {
    asm volatile("ldmatrix.sync.aligned.m8n8.x4.shared.b16 {%0,%1,%2,%3}, [%4];"
                 : "=r"(r0), "=r"(r1), "=r"(r2), "=r"(r3) : "r"(addr));
}

__global__ void __launch_bounds__(256, 2) k_gemm() {
    __shared__ __align__(16) uint8_t sA[128 * 128];   // 128 rows x 64 halves
    __shared__ __align__(16) uint8_t sB[128 * 128];

    const int tid  = threadIdx.x;
    const int warp = tid >> 5, lane = tid & 31;
    const int wm = warp & 3;            // m offset 32*wm
    const int wn = warp >> 2;           // n offset 64*wn
    const int n0 = blockIdx.x * 128;
    const int p0 = blockIdx.y * 128;
    const __half* A  = (const __half*)g_A;
    const __half* Bm = (const __half*)g_B;
    const uint32_t sa = smem_u32(sA);
    const uint32_t sbb = smem_u32(sB);

    // staging: 4 uint4 each for A and B; thread covers (row = it*32 + tid>>3,
    // chunk c = tid&7). swizzled store offset = row*128 + (c^(row&7))*16.
    const int srow = tid >> 3;
    const int sc   = tid & 7;
    uint4 st[8];

    float acc[2][8][4];
    #pragma unroll
    for (int mt = 0; mt < 2; mt++)
        #pragma unroll
        for (int nt = 0; nt < 8; nt++)
            #pragma unroll
            for (int q = 0; q < 4; q++) acc[mt][nt][q] = 0.0f;

    #pragma unroll
    for (int it = 0; it < 4; it++) {
        const int row = it * 32 + srow;
        st[it]     = *reinterpret_cast<const uint4*>(A  + (size_t)(p0 + row) * KPAD + sc * 8);
        st[it + 4] = *reinterpret_cast<const uint4*>(Bm + (size_t)(n0 + row) * KPAD + sc * 8);
    }

    #pragma unroll 1
    for (int c = 0; c < NCH; c++) {
        __syncthreads();
        #pragma unroll
        for (int it = 0; it < 4; it++) {
            const int row = it * 32 + srow;
            const int off = row * 128 + ((sc ^ (row & 7)) << 4);
            *reinterpret_cast<uint4*>(sA + off) = st[it];
            *reinterpret_cast<uint4*>(sB + off) = st[it + 4];
        }
        __syncthreads();

        if (c + 1 < NCH) {
            const size_t kof = (size_t)(c + 1) * 64;
            #pragma unroll
            for (int it = 0; it < 4; it++) {
                const int row = it * 32 + srow;
                st[it]     = *reinterpret_cast<const uint4*>(A  + (size_t)(p0 + row) * KPAD + kof + sc * 8);
                st[it + 4] = *reinterpret_cast<const uint4*>(Bm + (size_t)(n0 + row) * KPAD + kof + sc * 8);
            }
        }

        #pragma unroll
        for (int ks = 0; ks < 4; ks++) {
            const int kch = ks * 2 + (lane >> 4);   // 16B chunk index (0..7)
            // A fragments (2 m-tiles)
            uint32_t af[2][4];
            #pragma unroll
            for (int mt = 0; mt < 2; mt++) {
                const int r = wm * 32 + mt * 16 + (lane & 15);
                ldsm4(af[mt][0], af[mt][1], af[mt][2], af[mt][3],
                      sa + r * 128 + ((kch ^ (r & 7)) << 4));
            }
            // B fragments: 4 LDSM.x4, each covers two n8 tiles
            #pragma unroll
            for (int nt2 = 0; nt2 < 4; nt2++) {
                const int r = wn * 64 + nt2 * 16 + (lane & 15);
                uint32_t b0, b1, b2, b3;
                ldsm4(b0, b1, b2, b3, sbb + r * 128 + ((kch ^ (r & 7)) << 4));
                // tile 2*nt2: {b0,b2}; tile 2*nt2+1: {b1,b3}
                mma16816(acc[0][2 * nt2],     af[0][0], af[0][1], af[0][2], af[0][3], b0, b2);
                mma16816(acc[1][2 * nt2],     af[1][0], af[1][1], af[1][2], af[1][3], b0, b2);
                mma16816(acc[0][2 * nt2 + 1], af[0][0], af[0][1], af[0][2], af[0][3], b1, b3);
                mma16816(acc[1][2 * nt2 + 1], af[1][0], af[1][1], af[1][2], af[1][3], b1, b3);
            }
        }
    }

    #pragma unroll
    for (int mt = 0; mt < 2; mt++) {
        const int m = p0 + wm * 32 + mt * 16 + (lane >> 2);
        #pragma unroll
        for (int nt = 0; nt < 8; nt++) {
            const int n = n0 + wn * 64 + nt * 8 + (lane & 3) * 2;
            float2 lo = make_float2(acc[mt][nt][0], acc[mt][nt][1]);
            float2 hi = make_float2(acc[mt][nt][2], acc[mt][nt][3]);
            *reinterpret_cast<float2*>(g_Ih + (size_t)m * NHID + n) = lo;
            *reinterpret_cast<float2*>(g_Ih + (size_t)(m + 8) * NHID + n) = hi;
        }
    }
}

// --------------------------------------------------------------------------
// k3: hidden LIF + fused output-layer neg contributions.
// --------------------------------------------------------------------------
__global__ void __launch_bounds__(256) k_lif_hidden(const float* __restrict__ w2,
                                                    float* __restrict__ hs_out) {
    __shared__ float ss[256 * 41];
    const int tid = threadIdx.x;
    const int warp = tid >> 5, lane = tid & 31;
    const int bh = blockIdx.x * 256 + tid;
    const int b = bh >> 10;
    const int h = bh & 1023;
    const float* Ibase = g_Ih + (size_t)b * NHID + h;
    const int row0 = blockIdx.x * 256;

    float v = 0.0f;
    for (int tc = 0; tc < TT; tc += 40) {
        #pragma unroll
        for (int j = 0; j < 40; j++) {
            float I = Ibase[(size_t)(tc + j) * (BSZ * NHID)];
            v = __fadd_rn(__fadd_rn(v, __fmul_rn(ALPHA, -v)), I);
            float s;
            if (v >= 1.0f) { s = 1.0f; v = 0.0f; }
            else {
                s = 0.0f;
                float* pb = g_part + ((size_t)b * TT + (tc + j)) * NOUT;
                #pragma unroll
                for (int o = 0; o < NOUT; o++)
                    atomicAdd(pb + o, fmaxf(w2[(size_t)h * NOUT + o], 0.0f));
            }
            ss[tid * 41 + j] = s;
        }
        __syncthreads();
        #pragma unroll 1
        for (int r = 0; r < 32; r++) {
            const int row = warp * 32 + r;
            float* ob = hs_out + (size_t)(row0 + row) * TT + tc;
            #pragma unroll
            for (int j = lane; j < 40; j += 32)
                ob[j] = ss[row * 41 + j];
        }
        __syncthreads();
    }
}

// --------------------------------------------------------------------------
// k4b: sequential output LIF + firing rates. thread per (b,o).
// --------------------------------------------------------------------------
__global__ void k_out_lif(const float* __restrict__ w2,
                          float* __restrict__ os_out,
                          float* __restrict__ fr_out) {
    const int gid = blockIdx.x * blockDim.x + threadIdx.x;
    if (gid >= BSZ * NOUT) return;
    const int b = gid / NOUT;
    const int o = gid - b * NOUT;

    float colsum = 0.0f;
    for (int h = 0; h < NHID; h++)
        colsum += fmaxf(w2[(size_t)h * NOUT + o], 0.0f);

    const float* pb = g_part + (size_t)b * TT * NOUT + o;
    float v = 0.0f, cnt = 0.0f;
    float* ob = os_out + ((size_t)b * NOUT + o) * TT;
    for (int t = 0; t < TT; t++) {
        float I = (t > 0) ? (colsum - pb[(size_t)(t - 1) * NOUT]) : 0.0f;
        v = __fadd_rn(__fadd_rn(v, __fmul_rn(ALPHA, -v)), I);
        float s = (v >= 1.0f) ? 1.0f : 0.0f;
        if (v >= 1.0f) v = 0.0f;
        ob[t] = s;
        cnt += s;
    }
    fr_out[gid] = cnt / (float)TT;
}

// --------------------------------------------------------------------------
extern "C" void kernel_launch(void* const* d_in, const int* in_sizes, int n_in,
                              void* d_out, int out_size) {
    const float* sp = (const float*)d_in[0];   // (128, 784, 200)
    const float* w1 = (const float*)d_in[1];   // (784, 1024)
    const float* w2 = (const float*)d_in[2];   // (1024, 10)

    float* hs = (float*)d_out;                          // (B, NHID, T)
    float* os = hs + (size_t)BSZ * NHID * TT;           // (B, NOUT, T)
    float* fr = os + (size_t)BSZ * NOUT * TT;           // (B, NOUT)

    kA_stage<<<dim3(BSZ, 26), 256, 32 * 201 * sizeof(float)>>>(sp);
    kB_stage<<<dim3(32, 26), 256>>>(w1);
    k_zero<<<(BSZ * TT * NOUT / 4 + 255) / 256, 256>>>();
    k_gemm<<<dim3(NHID / 128, NPAIR / 128), 256>>>();
    k_lif_hidden<<<(BSZ * NHID) / 256, 256>>>(w2, hs);
    k_out_lif<<<5, 256>>>(w2, os, fr);
}

// round 9
// speedup vs baseline: 2.9933x; 1.0875x over previous
#include <cuda_runtime.h>
#include <cuda_fp16.h>
#include <cstdint>

#define BSZ   128
#define NIN   784
#define NHID  1024
#define NOUT  10
#define TT    200
#define NPAIR (TT * BSZ)          // 25600
#define ALPHA 0.05f
#define KPAD  832                  // 13 * 64 (K padded with zeros)
#define NCH   13                   // K chunks of 64

// -------------------- scratch (static device globals) ---------------------
__device__ unsigned short g_A[(size_t)NPAIR * KPAD];   // fp16 spikes  (pair, k)
__device__ unsigned short g_B[(size_t)NHID * KPAD];    // fp16 relu(w1)^T (n, k)
__device__ unsigned short g_Ih[(size_t)NPAIR * NHID];  // fp16 I_h (pair, h)
__device__ float          g_part[(size_t)BSZ * TT * NOUT]; // neg sums (b,t,o)

// --------------------------------------------------------------------------
// kA: stage spikes as fp16 A[(t*B+b), i] with K padded to 832.
// --------------------------------------------------------------------------
__global__ void __launch_bounds__(256) kA_stage(const float* __restrict__ sp) {
    extern __shared__ float tile[];   // [32][201]
    const int b = blockIdx.x;
    const int i0 = blockIdx.y * 32;
    for (int l = threadIdx.x; l < 32 * 200; l += 256) {
        int ii = l / 200, t = l - ii * 200;
        int i = i0 + ii;
        float v = (i < NIN) ? sp[((size_t)b * NIN + i) * TT + t] : 0.0f;
        tile[ii * 201 + t] = v;
    }
    __syncthreads();
    __half* A = (__half*)g_A;
    for (int l = threadIdx.x; l < 32 * 200; l += 256) {
        int t = l >> 5, ii = l & 31;
        A[((size_t)t * BSZ + b) * KPAD + i0 + ii] = __float2half(tile[ii * 201 + t]);
    }
}

// --------------------------------------------------------------------------
// kB: stage relu(w1)^T as fp16 B[n, i], K padded to 832. Blocks with y==26
// zero g_part instead (folded k_zero).
// --------------------------------------------------------------------------
__global__ void __launch_bounds__(256) kB_stage(const float* __restrict__ w1) {
    if (blockIdx.y == 26) {
        const int base = (blockIdx.x * 256 + threadIdx.x) * 4;
        for (int idx = base; idx < BSZ * TT * NOUT; idx += 32 * 256 * 4)
            *reinterpret_cast<float4*>(g_part + idx) = make_float4(0.f, 0.f, 0.f, 0.f);
        return;
    }
    __shared__ float tile[32][33];
    const int n0 = blockIdx.x * 32;
    const int i0 = blockIdx.y * 32;
    const int r = threadIdx.x >> 5, c = threadIdx.x & 31;
    for (int rr = r; rr < 32; rr += 8) {
        int i = i0 + rr;
        tile[rr][c] = (i < NIN) ? fmaxf(w1[(size_t)i * NHID + n0 + c], 0.0f) : 0.0f;
    }
    __syncthreads();
    __half* B = (__half*)g_B;
    for (int cc = r; cc < 32; cc += 8)
        B[((size_t)(n0 + cc)) * KPAD + i0 + c] = __float2half(tile[c][cc]);
}

// --------------------------------------------------------------------------
// k_gemm: I_h = A @ B^T, f16 HMMA with f16 accumulation, cp.async 3-stage.
// CTA 128x128, 4 warps, warp tile 64x64. XOR-swizzled SMEM + ldmatrix.
// --------------------------------------------------------------------------
__device__ __forceinline__ uint32_t smem_u32(const void* p) {
    uint32_t a;
    asm("{ .reg .u64 t; cvta.to.shared.u64 t, %1; cvt.u32.u64 %0, t; }"
        : "=r"(a) : "l"(p));
    return a;
}
__device__ __forceinline__ void mma16816h(uint32_t* c, uint32_t a0, uint32_t a1,
                                          uint32_t a2, uint32_t a3,
                                          uint32_t b0, uint32_t b1) {
    asm volatile(
        "mma.sync.aligned.m16n8k16.row.col.f16.f16.f16.f16 "
        "{%0,%1}, {%2,%3,%4,%5}, {%6,%7}, {%0,%1};"
        : "+r"(c[0]), "+r"(c[1])
        : "r"(a0), "r"(a1), "r"(a2), "r"(a3), "r"(b0), "r"(b1));
}
__device__ __forceinline__ void ldsm4(uint32_t& r0, uint32_t& r1,
                                      uint32_t& r2, uint32_t& r3, uint32_t addr) {
    asm volatile("ldmatrix.sync.aligned.m8n8.x4.shared.b16 {%0,%1,%2,%3}, [%4];"
                 : "=r"(r0), "=r"(r1), "=r"(r2), "=r"(r3) : "r"(addr));
}
__device__ __forceinline__ void cp16(uint32_t saddr, const void* gptr) {
    asm volatile("cp.async.cg.shared.global [%0], [%1], 16;"
                 :: "r"(saddr), "l"(gptr));
}
#define CP_COMMIT() asm volatile("cp.async.commit_group;" ::: "memory")
#define CP_WAIT(n)  asm volatile("cp.async.wait_group %0;" :: "n"(n) : "memory")

#define STAGE_BYTES 32768

__global__ void __launch_bounds__(128, 2) k_gemm() {
    __shared__ __align__(16) uint8_t smbuf[3 * STAGE_BYTES];

    const int tid  = threadIdx.x;
    const int warp = tid >> 5, lane = tid & 31;
    const int wm = warp & 1;            // m offset 64*wm
    const int wn = warp >> 1;           // n offset 64*wn
    const int n0 = blockIdx.x * 128;
    const int p0 = blockIdx.y * 128;
    const __half* A  = (const __half*)g_A;
    const __half* Bm = (const __half*)g_B;
    const uint32_t sbase = smem_u32(smbuf);

    // staging map: thread covers rows it*16 + (tid>>3), chunk c = tid&7 (16B)
    const int srow = tid >> 3;
    const int sc   = tid & 7;

    uint32_t acc[4][8][2];
    #pragma unroll
    for (int mt = 0; mt < 4; mt++)
        #pragma unroll
        for (int nt = 0; nt < 8; nt++) { acc[mt][nt][0] = 0u; acc[mt][nt][1] = 0u; }

    // issue one chunk's loads into stage s
    auto issue = [&](int c, int s) {
        const uint32_t st0 = sbase + s * STAGE_BYTES;
        const size_t kof = (size_t)c * 64 + sc * 8;
        #pragma unroll
        for (int it = 0; it < 8; it++) {
            const int row = it * 16 + srow;
            const int off = row * 128 + ((sc ^ (row & 7)) << 4);
            cp16(st0 + off,         A  + (size_t)(p0 + row) * KPAD + kof);
            cp16(st0 + 16384 + off, Bm + (size_t)(n0 + row) * KPAD + kof);
        }
        CP_COMMIT();
    };

    issue(0, 0);
    issue(1, 1);

    #pragma unroll 1
    for (int c = 0; c < NCH; c++) {
        if (c + 2 < NCH) { CP_WAIT(1); } else { CP_WAIT(0); }
        __syncthreads();
        if (c + 2 < NCH) issue(c + 2, (c + 2) % 3);

        const uint32_t sa = sbase + (c % 3) * STAGE_BYTES;
        const uint32_t sb = sa + 16384;

        #pragma unroll
        for (int ks = 0; ks < 4; ks++) {
            const int kch = ks * 2 + (lane >> 4);
            uint32_t af[4][4];
            #pragma unroll
            for (int mt = 0; mt < 4; mt++) {
                const int r = wm * 64 + mt * 16 + (lane & 15);
                ldsm4(af[mt][0], af[mt][1], af[mt][2], af[mt][3],
                      sa + r * 128 + ((kch ^ (r & 7)) << 4));
            }
            #pragma unroll
            for (int nt2 = 0; nt2 < 4; nt2++) {
                const int r = wn * 64 + nt2 * 16 + (lane & 15);
                uint32_t b0, b1, b2, b3;
                ldsm4(b0, b1, b2, b3, sb + r * 128 + ((kch ^ (r & 7)) << 4));
                #pragma unroll
                for (int mt = 0; mt < 4; mt++) {
                    mma16816h(acc[mt][2 * nt2],     af[mt][0], af[mt][1], af[mt][2], af[mt][3], b0, b2);
                    mma16816h(acc[mt][2 * nt2 + 1], af[mt][0], af[mt][1], af[mt][2], af[mt][3], b1, b3);
                }
            }
        }
        __syncthreads();
    }

    // epilogue: f16 acc -> fp16 g_Ih (half2 stores)
    __half* Ih = (__half*)g_Ih;
    #pragma unroll
    for (int mt = 0; mt < 4; mt++) {
        const int m = p0 + wm * 64 + mt * 16 + (lane >> 2);
        #pragma unroll
        for (int nt = 0; nt < 8; nt++) {
            const int n = n0 + wn * 64 + nt * 8 + (lane & 3) * 2;
            *reinterpret_cast<uint32_t*>(Ih + (size_t)m * NHID + n)       = acc[mt][nt][0];
            *reinterpret_cast<uint32_t*>(Ih + (size_t)(m + 8) * NHID + n) = acc[mt][nt][1];
        }
    }
}

// --------------------------------------------------------------------------
// k3: hidden LIF + fused output-layer neg contributions. fp16 I reads.
// --------------------------------------------------------------------------
__global__ void __launch_bounds__(256) k_lif_hidden(const float* __restrict__ w2,
                                                    float* __restrict__ hs_out) {
    __shared__ float ss[256 * 41];
    const int tid = threadIdx.x;
    const int warp = tid >> 5, lane = tid & 31;
    const int bh = blockIdx.x * 256 + tid;
    const int b = bh >> 10;
    const int h = bh & 1023;
    const __half* Ibase = (const __half*)g_Ih + (size_t)b * NHID + h;
    const int row0 = blockIdx.x * 256;

    float v = 0.0f;
    for (int tc = 0; tc < TT; tc += 40) {
        #pragma unroll
        for (int j = 0; j < 40; j++) {
            float I = __half2float(Ibase[(size_t)(tc + j) * (BSZ * NHID)]);
            v = __fadd_rn(__fadd_rn(v, __fmul_rn(ALPHA, -v)), I);
            float s;
            if (v >= 1.0f) { s = 1.0f; v = 0.0f; }
            else {
                s = 0.0f;
                float* pb = g_part + ((size_t)b * TT + (tc + j)) * NOUT;
                #pragma unroll
                for (int o = 0; o < NOUT; o++)
                    atomicAdd(pb + o, fmaxf(w2[(size_t)h * NOUT + o], 0.0f));
            }
            ss[tid * 41 + j] = s;
        }
        __syncthreads();
        #pragma unroll 1
        for (int r = 0; r < 32; r++) {
            const int row = warp * 32 + r;
            float* ob = hs_out + (size_t)(row0 + row) * TT + tc;
            #pragma unroll
            for (int j = lane; j < 40; j += 32)
                ob[j] = ss[row * 41 + j];
        }
        __syncthreads();
    }
}

// --------------------------------------------------------------------------
// k4b: sequential output LIF + firing rates. thread per (b,o).
// --------------------------------------------------------------------------
__global__ void k_out_lif(const float* __restrict__ w2,
                          float* __restrict__ os_out,
                          float* __restrict__ fr_out) {
    const int gid = blockIdx.x * blockDim.x + threadIdx.x;
    if (gid >= BSZ * NOUT) return;
    const int b = gid / NOUT;
    const int o = gid - b * NOUT;

    float colsum = 0.0f;
    for (int h = 0; h < NHID; h++)
        colsum += fmaxf(w2[(size_t)h * NOUT + o], 0.0f);

    const float* pb = g_part + (size_t)b * TT * NOUT + o;
    float v = 0.0f, cnt = 0.0f;
    float* ob = os_out + ((size_t)b * NOUT + o) * TT;
    for (int t = 0; t < TT; t++) {
        float I = (t > 0) ? (colsum - pb[(size_t)(t - 1) * NOUT]) : 0.0f;
        v = __fadd_rn(__fadd_rn(v, __fmul_rn(ALPHA, -v)), I);
        float s = (v >= 1.0f) ? 1.0f : 0.0f;
        if (v >= 1.0f) v = 0.0f;
        ob[t] = s;
        cnt += s;
    }
    fr_out[gid] = cnt / (float)TT;
}

// --------------------------------------------------------------------------
extern "C" void kernel_launch(void* const* d_in, const int* in_sizes, int n_in,
                              void* d_out, int out_size) {
    const float* sp = (const float*)d_in[0];   // (128, 784, 200)
    const float* w1 = (const float*)d_in[1];   // (784, 1024)
    const float* w2 = (const float*)d_in[2];   // (1024, 10)

    float* hs = (float*)d_out;                          // (B, NHID, T)
    float* os = hs + (size_t)BSZ * NHID * TT;           // (B, NOUT, T)
    float* fr = os + (size_t)BSZ * NOUT * TT;           // (B, NOUT)

    kA_stage<<<dim3(BSZ, 26), 256, 32 * 201 * sizeof(float)>>>(sp);
    kB_stage<<<dim3(32, 27), 256>>>(w1);
    k_gemm<<<dim3(NHID / 128, NPAIR / 128), 128>>>();
    k_lif_hidden<<<(BSZ * NHID) / 256, 256>>>(w2, hs);
    k_out_lif<<<5, 256>>>(w2, os, fr);
}